// round 14
// baseline (speedup 1.0000x reference)
#include <cuda_runtime.h>
#include <cstddef>

// ---------------- problem constants ----------------
#define C      64
#define CPAD   68          // padded row stride (floats) -> conflict-free LDS.128
#define NATOMS 200000
#define NPATH5 100000
#define LEN5   5
#define NPATH6 80000
#define LEN6   6
#define NPP5   5           // paths per group, L=5 (mix GEMM factored out -> fits)
#define NPP6   4           // paths per group, L=6
#define PBLK   152         // blocks per path sub-problem (merged kernel)
#define RAT    8           // atoms per tile in zmix/atoms (proven (256,3) config)

// ---------------- scratch (device globals; zero-initialized at load) -------
// g_sum/g_cnt are restored to zero by atoms_kernel after consuming (replay safe).
// g_z5/g_z6 are fully overwritten by zmix_kernel every call.
__device__ float g_sum5[(size_t)NATOMS * C];
__device__ float g_sum6[(size_t)NATOMS * C];
__device__ float g_cnt5[NATOMS];
__device__ float g_cnt6[NATOMS];
__device__ float g_z5[(size_t)NATOMS * C];
__device__ float g_z6[(size_t)NATOMS * C];

using u64 = unsigned long long;

// ---------------- packed fp32 helpers (sm_103a FFMA2 path) ----------------
__device__ __forceinline__ void lds2(u64 &a, u64 &b, const float *p) {
    unsigned s = (unsigned)__cvta_generic_to_shared(p);
    asm volatile("ld.shared.v2.b64 {%0,%1}, [%2];" : "=l"(a), "=l"(b) : "r"(s));
}
__device__ __forceinline__ void fma2(u64 &acc, u64 a, u64 b) {
    asm volatile("fma.rn.f32x2 %0, %1, %2, %0;" : "+l"(acc) : "l"(a), "l"(b));
}
__device__ __forceinline__ float hsum2(u64 a) {
    float lo, hi;
    asm volatile("mov.b64 {%0,%1}, %2;" : "=f"(lo), "=f"(hi) : "l"(a));
    return lo + hi;
}
__device__ __forceinline__ void red4(float *p, float4 v) {
    asm volatile("red.global.add.v4.f32 [%0], {%1,%2,%3,%4};"
                 :: "l"(p), "f"(v.x), "f"(v.y), "f"(v.z), "f"(v.w) : "memory");
}
// named barrier for a 64-thread group (ids 1..8; __syncthreads owns id 0)
__device__ __forceinline__ void barg(int id) {
    asm volatile("bar.sync %0, 64;" :: "r"(id) : "memory");
}
// cp.async global->shared
__device__ __forceinline__ void cpa16(float *s, const float *g) {
    unsigned sa = (unsigned)__cvta_generic_to_shared(s);
    asm volatile("cp.async.cg.shared.global [%0], [%1], 16;" :: "r"(sa), "l"(g));
}
__device__ __forceinline__ void cpa4(float *s, const float *g) {
    unsigned sa = (unsigned)__cvta_generic_to_shared(s);
    asm volatile("cp.async.ca.shared.global [%0], [%1], 4;" :: "r"(sa), "l"(g));
}
__device__ __forceinline__ void cp_commit() {
    asm volatile("cp.async.commit_group;" ::: "memory");
}
__device__ __forceinline__ void cp_wait0() {
    asm volatile("cp.async.wait_group 0;" ::: "memory");
}
__device__ __forceinline__ void stg16_zero(float *p) {
    asm volatile("st.global.v4.f32 [%0], {%1,%1,%1,%1};" :: "l"(p), "f"(0.f) : "memory");
}

// ---------------- zmix: z = relu(x @ Wa.T + ba) for all atoms --------------
// (256,3) / RAT=8 — proven 92us configuration.
__global__ __launch_bounds__(256, 3) void zmix_kernel(
    const float *__restrict__ x,
    const float *__restrict__ Wa5, const float *__restrict__ ba5,
    const float *__restrict__ Wa6, const float *__restrict__ ba6)
{
    extern __shared__ float smem[];
    float *W5s = smem;
    float *W6s = W5s + C * CPAD;
    float *b5s = W6s + C * CPAD;
    float *b6s = b5s + C;
    float *tA  = b6s + C;             // [4 groups][RAT][C]
    float *tB  = tA + 4 * RAT * C;

    int tid = threadIdx.x;
    for (int i = tid; i < C * C; i += 256) {
        W5s[(i / C) * CPAD + (i % C)] = Wa5[i];
        W6s[(i / C) * CPAD + (i % C)] = Wa6[i];
    }
    if (tid < C) { b5s[tid] = ba5[tid]; b6s[tid] = ba6[tid]; }
    __syncthreads();

    int g = tid >> 6, t = tid & 63;
    int bid = g + 1;
    float *mA = tA + g * RAT * C;
    float *mB = tB + g * RAT * C;
    int nq = NATOMS / RAT;            // 25000 exact
    int qstride = gridDim.x * 4;
    int iters = (nq + qstride - 1) / qstride;
    int q0 = blockIdx.x * 4 + g;

    if (q0 < nq) {
        int a0 = q0 * RAT;
        for (int item = t; item < RAT * 16; item += 64) {
            int rr = item >> 4, qq = item & 15;
            cpa16(mA + rr * C + qq * 4, x + (size_t)(a0 + rr) * C + qq * 4);
        }
    }
    cp_commit();

    int pb = 0;
    for (int it = 0; it < iters; ++it) {
        int q = q0 + it * qstride;
        bool act = q < nq;
        float *mc = pb ? mB : mA;
        float *mn = pb ? mA : mB;

        cp_wait0();
        barg(bid);

        {
            int q2 = q0 + (it + 1) * qstride;
            if (q2 < nq) {
                int a0 = q2 * RAT;
                for (int item = t; item < RAT * 16; item += 64) {
                    int rr = item >> 4, qq = item & 15;
                    cpa16(mn + rr * C + qq * 4, x + (size_t)(a0 + rr) * C + qq * 4);
                }
            }
            cp_commit();
        }

        if (act) {
            int a0 = q * RAT;
            u64 a5[RAT], a6[RAT];
#pragma unroll
            for (int r = 0; r < RAT; r++) { a5[r] = 0ull; a6[r] = 0ull; }
            const float *w5r = W5s + t * CPAD;
            const float *w6r = W6s + t * CPAD;
#pragma unroll 2
            for (int c = 0; c < 16; c++) {
                u64 w50, w51, w60, w61;
                lds2(w50, w51, w5r + 4 * c);
                lds2(w60, w61, w6r + 4 * c);
#pragma unroll
                for (int r = 0; r < RAT; r++) {
                    u64 x0, x1;
                    lds2(x0, x1, mc + r * C + 4 * c);
                    fma2(a5[r], w50, x0); fma2(a5[r], w51, x1);
                    fma2(a6[r], w60, x0); fma2(a6[r], w61, x1);
                }
            }
#pragma unroll
            for (int r = 0; r < RAT; r++) {
                int a = a0 + r;
                g_z5[(size_t)a * C + t] = fmaxf(hsum2(a5[r]) + b5s[t], 0.f);
                g_z6[(size_t)a * C + t] = fmaxf(hsum2(a6[r]) + b6s[t], 0.f);
            }
        }
        pb ^= 1;
    }
}

// ---------------- conv pass: h = Wc(k=3) * vp + bias (no write) ------------
template <int L, int NP>
__device__ __forceinline__ void conv_pass(
    const float *vp, const float *w0r, const float *w1r, const float *w2r,
    float bias, float (&h)[NP][L])
{
    u64 acc[NP][L];
#pragma unroll
    for (int j = 0; j < NP; j++)
#pragma unroll
        for (int l = 0; l < L; l++) acc[j][l] = 0ull;
#pragma unroll 2
    for (int c = 0; c < 16; c++) {
        u64 wa0, wa1, wb0, wb1, wc0, wc1;
        lds2(wa0, wa1, w0r + 4 * c);
        lds2(wb0, wb1, w1r + 4 * c);
        lds2(wc0, wc1, w2r + 4 * c);
#pragma unroll
        for (int j = 0; j < NP; j++) {
            u64 a0[L], a1[L];
#pragma unroll
            for (int l = 0; l < L; l++)
                lds2(a0[l], a1[l], vp + (j * L + l) * C + 4 * c);
#pragma unroll
            for (int l = 0; l < L; l++) {
                if (l > 0)     { fma2(acc[j][l], wa0, a0[l - 1]); fma2(acc[j][l], wa1, a1[l - 1]); }
                                 fma2(acc[j][l], wb0, a0[l]);     fma2(acc[j][l], wb1, a1[l]);
                if (l < L - 1) { fma2(acc[j][l], wc0, a0[l + 1]); fma2(acc[j][l], wc1, a1[l + 1]); }
            }
        }
    }
#pragma unroll
    for (int j = 0; j < NP; j++)
#pragma unroll
        for (int l = 0; l < L; l++)
            h[j][l] = hsum2(acc[j][l]) + bias;
}

// ---------------- fused path body (gathers precomputed z; conv only) -------
template <int L, int NP>
__device__ __forceinline__ void path_body(
    float *smem, int blk, int nblk,
    const float *__restrict__ z, const float *__restrict__ xp_in,
    const int *__restrict__ row,
    const float *__restrict__ Wc, const float *__restrict__ bc,
    float *__restrict__ xp_out, int P, float *sum, float *cnt)
{
    constexpr int NV = NP * L;
    constexpr int GI = (NV * 16 + 63) / 64;   // float4 items per thread

    float *Wc_s = smem;                      // 6*C*CPAD
    float *bc_s = Wc_s + 6 * C * CPAD;       // 2*C
    float *vA   = bc_s + 2 * C;              // 8*NV*C (buffer A)
    float *vB   = vA + 8 * NV * C;           // 8*NV*C (buffer B)
    int   *rows = (int *)(vB + 8 * NV * C);  // 8*2*NV

    int tid = threadIdx.x;
    for (int i = tid; i < 6 * C * C; i += 512) {
        int m = i / (C * C);
        int r = i - m * C * C;
        int ci = r / C, co = r - ci * C;
        Wc_s[(m * C + co) * CPAD + ci] = Wc[i];
    }
    if (tid < 2 * C) bc_s[tid] = bc[tid];
    __syncthreads();

    int g = tid >> 6, t = tid & 63;
    int bid = g + 1;
    float *vpa = vA + g * NV * C;
    float *vpb = vB + g * NV * C;
    int *rp0 = rows + g * 2 * NV;
    int *rp1 = rp0 + NV;
    int NG = nblk * 8;
    int iters = (P + NG * NP - 1) / (NG * NP);
    int G = blk * 8 + g;

    // prologue: rows_0 -> rp0; cp.async gather_0 (z rows) -> vpa
    if (t < NV) {
        int j = t / L, l = t - j * L;
        int p = G * NP + j;
        rp0[t] = (p < P) ? row[p * L + l] : 0;
    }
    barg(bid);
    for (int item = t; item < NV * 16; item += 64) {
        int r = item >> 4, q = item & 15;
        cpa16(vpa + r * C + q * 4, z + (size_t)rp0[r] * C + q * 4);
    }
    cp_commit();

    int pb = 0;
    for (int it = 0; it < iters; ++it) {
        int pbase = (it * NG + G) * NP;
        int pnext = ((it + 1) * NG + G) * NP;
        float *vp = pb ? vpb : vpa;
        float *vn = pb ? vpa : vpb;
        int *rp_cur = pb ? rp1 : rp0;
        int *rp_nxt = pb ? rp0 : rp1;

        // phase 1: issue rows_{i+1} + xp_in loads (float4 item layout); wait
        int rnext = 0;
        if (t < NV) {
            int j = t / L, l = t - j * L;
            int p = pnext + j;
            if (p < P) rnext = row[p * L + l];
        }
        float4 xi[GI];
#pragma unroll
        for (int ii = 0; ii < GI; ii++) {
            int item = t + 64 * ii;
            xi[ii] = make_float4(0.f, 0.f, 0.f, 0.f);
            if (item < NV * 16) {
                int r = item >> 4, q = item & 15;
                int j = r / L;
                if (pbase + j < P)
                    xi[ii] = ((const float4 *)(xp_in + (size_t)(pbase + j) * L * C))
                                 [(r - j * L) * 16 + q];
            }
        }
        cp_wait0();
        barg(bid);  // gathered z in vp visible to whole group

        // phase 2: v = z + xp_in  (float4 item layout)
#pragma unroll
        for (int ii = 0; ii < GI; ii++) {
            int item = t + 64 * ii;
            if (item < NV * 16) {
                float4 v = ((float4 *)vp)[item];
                v.x += xi[ii].x; v.y += xi[ii].y; v.z += xi[ii].z; v.w += xi[ii].w;
                ((float4 *)vp)[item] = v;
            }
        }
        if (t < NV) rp_nxt[t] = rnext;
        barg(bid);

        // phase 3: conv depth 0
        float h[NP][L];
        conv_pass<L, NP>(vp, Wc_s + (0 * C + t) * CPAD, Wc_s + (1 * C + t) * CPAD,
                         Wc_s + (2 * C + t) * CPAD, bc_s[t], h);
        barg(bid);
#pragma unroll
        for (int j = 0; j < NP; j++)
#pragma unroll
            for (int l = 0; l < L; l++)
                vp[(j * L + l) * C + t] += fmaxf(h[j][l], 0.f);

        // phase 3.5: issue gather_{i+1} into vn (register-free; hides under d1)
        for (int item = t; item < NV * 16; item += 64) {
            int r = item >> 4, q = item & 15;
            cpa16(vn + r * C + q * 4, z + (size_t)rp_nxt[r] * C + q * 4);
        }
        cp_commit();
        barg(bid);

        // phase 4: conv depth 1
        conv_pass<L, NP>(vp, Wc_s + (3 * C + t) * CPAD, Wc_s + (4 * C + t) * CPAD,
                         Wc_s + (5 * C + t) * CPAD, bc_s[C + t], h);
        barg(bid);
#pragma unroll
        for (int j = 0; j < NP; j++)
#pragma unroll
            for (int l = 0; l < L; l++)
                vp[(j * L + l) * C + t] += fmaxf(h[j][l], 0.f);
        barg(bid);

        // phase 5: write xp_out + scatter into atom accumulators.
        for (int item = t; item < NV * 16; item += 64) {
            int r = item >> 4, q = item & 15;
            int j = r / L;
            if (pbase + j < P) {
                float4 v = ((float4 *)vp)[r * 16 + q];
                ((float4 *)(xp_out + (size_t)(pbase + j) * L * C))[(r - j * L) * 16 + q] = v;
                red4(sum + (size_t)rp_cur[r] * C + q * 4, v);
            }
        }
        if (t < NV && pbase + t / L < P)
            atomicAdd(&cnt[rp_cur[t]], 1.0f);
        pb ^= 1;
    }
}

// ---------------- merged path kernel ----------------
__global__ __launch_bounds__(512, 1) void paths_kernel(
    const float *__restrict__ xp5, const float *__restrict__ xp6,
    const int *__restrict__ row5, const int *__restrict__ row6,
    const float *__restrict__ Wc5, const float *__restrict__ bc5,
    const float *__restrict__ Wc6, const float *__restrict__ bc6,
    float *__restrict__ xp5_out, float *__restrict__ xp6_out)
{
    extern __shared__ float smem[];
    if (blockIdx.x < PBLK)
        path_body<LEN5, NPP5>(smem, blockIdx.x, PBLK, g_z5, xp5, row5,
                              Wc5, bc5, xp5_out, NPATH5, g_sum5, g_cnt5);
    else
        path_body<LEN6, NPP6>(smem, blockIdx.x - PBLK, PBLK, g_z6, xp6, row6,
                              Wc6, bc6, xp6_out, NPATH6, g_sum6, g_cnt6);
}

// ---------------- atom kernel (cp.async pipelined, self-cleaning) ----------
// (256,3) / RAT=8 — proven configuration; zero-restore after compute issue.
__global__ __launch_bounds__(256, 3) void atoms_kernel(
    const float *__restrict__ x,
    const float *__restrict__ Wp5, const float *__restrict__ bp5,
    const float *__restrict__ Wp6, const float *__restrict__ bp6,
    float *__restrict__ xout)
{
    extern __shared__ float smem[];
    float *W5s = smem;
    float *W6s = W5s + C * CPAD;
    float *b5s = W6s + C * CPAD;
    float *b6s = b5s + C;
    float *msA = b6s + C;                 // [4 groups][2*RAT][C]
    float *msB = msA + 4 * 2 * RAT * C;
    float *cnA = msB + 4 * 2 * RAT * C;   // [4 groups][2*RAT]
    float *cnB = cnA + 4 * 2 * RAT;

    int tid = threadIdx.x;
    for (int i = tid; i < C * C; i += 256) {
        W5s[(i / C) * CPAD + (i % C)] = Wp5[i];
        W6s[(i / C) * CPAD + (i % C)] = Wp6[i];
    }
    if (tid < C) { b5s[tid] = bp5[tid]; b6s[tid] = bp6[tid]; }
    __syncthreads();

    int g = tid >> 6, t = tid & 63;
    int bid = g + 1;
    float *mA = msA + g * 2 * RAT * C;
    float *mB = msB + g * 2 * RAT * C;
    float *cA = cnA + g * 2 * RAT;
    float *cB = cnB + g * 2 * RAT;
    int nq = NATOMS / RAT;                // 25000 exact
    int qstride = gridDim.x * 4;
    int iters = (nq + qstride - 1) / qstride;
    int q0 = blockIdx.x * 4 + g;

    if (q0 < nq) {
        int a0 = q0 * RAT;
        for (int item = t; item < 2 * RAT * 16; item += 64) {
            int rr = item >> 4, qq = item & 15;
            const float *src = (rr < RAT)
                ? g_sum5 + (size_t)(a0 + rr) * C + qq * 4
                : g_sum6 + (size_t)(a0 + rr - RAT) * C + qq * 4;
            cpa16(mA + rr * C + qq * 4, src);
        }
        if (t < 2 * RAT)
            cpa4(cA + t, (t < RAT) ? g_cnt5 + a0 + t : g_cnt6 + a0 + t - RAT);
    }
    cp_commit();

    int pb = 0;
    for (int it = 0; it < iters; ++it) {
        int q = q0 + it * qstride;
        bool act = q < nq;
        float *mc = pb ? mB : mA;
        float *mn = pb ? mA : mB;
        float *cc2 = pb ? cB : cA;
        float *cn2 = pb ? cA : cB;

        cp_wait0();
        barg(bid);

        {
            int q2 = q0 + (it + 1) * qstride;
            if (q2 < nq) {
                int a0 = q2 * RAT;
                for (int item = t; item < 2 * RAT * 16; item += 64) {
                    int rr = item >> 4, qq = item & 15;
                    const float *src = (rr < RAT)
                        ? g_sum5 + (size_t)(a0 + rr) * C + qq * 4
                        : g_sum6 + (size_t)(a0 + rr - RAT) * C + qq * 4;
                    cpa16(mn + rr * C + qq * 4, src);
                }
                if (t < 2 * RAT)
                    cpa4(cn2 + t, (t < RAT) ? g_cnt5 + a0 + t : g_cnt6 + a0 + t - RAT);
            }
            cp_commit();
        }

        if (act) {
            int a0 = q * RAT;
            float c5[RAT], c6[RAT], xv[RAT];
#pragma unroll
            for (int r = 0; r < RAT; r++) {
                c5[r] = cc2[r];
                c6[r] = cc2[RAT + r];
                xv[r] = x[(size_t)(a0 + r) * C + t];
            }
            u64 a5[RAT], a6[RAT];
#pragma unroll
            for (int r = 0; r < RAT; r++) { a5[r] = 0ull; a6[r] = 0ull; }
            const float *w5r = W5s + t * CPAD;
            const float *w6r = W6s + t * CPAD;
#pragma unroll 2
            for (int c = 0; c < 16; c++) {
                u64 w50, w51, w60, w61;
                lds2(w50, w51, w5r + 4 * c);
                lds2(w60, w61, w6r + 4 * c);
#pragma unroll
                for (int r = 0; r < RAT; r++) {
                    u64 x0, x1;
                    lds2(x0, x1, mc + r * C + 4 * c);
                    fma2(a5[r], w50, x0); fma2(a5[r], w51, x1);
                    u64 y0, y1;
                    lds2(y0, y1, mc + (RAT + r) * C + 4 * c);
                    fma2(a6[r], w60, y0); fma2(a6[r], w61, y1);
                }
            }
#pragma unroll
            for (int r = 0; r < RAT; r++) {
                int a = a0 + r;
                float v = xv[r]
                        + fmaxf(hsum2(a5[r]) / fmaxf(c5[r], 1.f) + b5s[t], 0.f)
                        + fmaxf(hsum2(a6[r]) / fmaxf(c6[r], 1.f) + b6s[t], 0.f);
                xout[(size_t)a * C + t] = v;
            }

            // restore consumed global regions to zero (after compute issue)
            for (int item = t; item < 2 * RAT * 16; item += 64) {
                int rr = item >> 4, qq = item & 15;
                float *dst = (rr < RAT)
                    ? g_sum5 + (size_t)(a0 + rr) * C + qq * 4
                    : g_sum6 + (size_t)(a0 + rr - RAT) * C + qq * 4;
                stg16_zero(dst);
            }
            if (t < 2 * RAT)
                *((t < RAT) ? g_cnt5 + a0 + t : g_cnt6 + a0 + t - RAT) = 0.f;
        }
        pb ^= 1;
    }
}

// ---------------- launch ----------------
extern "C" void kernel_launch(void *const *d_in, const int *in_sizes, int n_in,
                              void *d_out, int out_size)
{
    const float *x    = (const float *)d_in[0];
    const float *xp5  = (const float *)d_in[1];
    const float *xp6  = (const float *)d_in[2];
    const int   *row5 = (const int *)d_in[3];
    // d_in[4] = col5 (identity arange), unused
    const int   *row6 = (const int *)d_in[5];
    // d_in[6] = col6 (identity arange), unused
    const float *Wa5 = (const float *)d_in[7];
    const float *ba5 = (const float *)d_in[8];
    const float *Wa6 = (const float *)d_in[9];
    const float *ba6 = (const float *)d_in[10];
    const float *Wp5 = (const float *)d_in[11];
    const float *bp5 = (const float *)d_in[12];
    const float *Wp6 = (const float *)d_in[13];
    const float *bp6 = (const float *)d_in[14];
    const float *Wc5 = (const float *)d_in[15];
    const float *bc5 = (const float *)d_in[16];
    const float *Wc6 = (const float *)d_in[17];
    const float *bc6 = (const float *)d_in[18];

    float *x_out   = (float *)d_out;
    float *xp5_out = x_out + (size_t)NATOMS * C;
    float *xp6_out = xp5_out + (size_t)NPATH5 * LEN5 * C;

    constexpr int NV5 = NPP5 * LEN5;   // 25
    constexpr int NV6 = NPP6 * LEN6;   // 24
    constexpr int smem_wts = (6 * C * CPAD + 2 * C) * 4;
    constexpr int smem5 = smem_wts + (2 * 8 * NV5 * C) * 4 + (8 * 2 * NV5) * 4;
    constexpr int smem6 = smem_wts + (2 * 8 * NV6 * C) * 4 + (8 * 2 * NV6) * 4;
    constexpr int smemP = (smem5 > smem6) ? smem5 : smem6;
    constexpr int smemA = (2 * C * CPAD + 2 * C + 2 * 4 * 2 * RAT * C + 2 * 4 * 2 * RAT) * 4;
    constexpr int smemZ = (2 * C * CPAD + 2 * C + 2 * 4 * RAT * C) * 4;

    static_assert(smemP < 227 * 1024, "path smem");
    static_assert(smemA < 76 * 1024, "atoms smem (3 CTAs/SM)");
    static_assert(smemZ < 76 * 1024, "zmix smem (3 CTAs/SM)");

    cudaFuncSetAttribute((const void *)paths_kernel,
                         cudaFuncAttributeMaxDynamicSharedMemorySize, smemP);
    cudaFuncSetAttribute((const void *)atoms_kernel,
                         cudaFuncAttributeMaxDynamicSharedMemorySize, smemA);
    cudaFuncSetAttribute((const void *)zmix_kernel,
                         cudaFuncAttributeMaxDynamicSharedMemorySize, smemZ);

    zmix_kernel<<<456, 256, smemZ>>>(x, Wa5, ba5, Wa6, ba6);

    paths_kernel<<<2 * PBLK, 512, smemP>>>(xp5, xp6, row5, row6,
                                           Wc5, bc5, Wc6, bc6,
                                           xp5_out, xp6_out);

    atoms_kernel<<<456, 256, smemA>>>(x, Wp5, bp5, Wp6, bp6, x_out);
}

// round 15
// speedup vs baseline: 1.0058x; 1.0058x over previous
#include <cuda_runtime.h>
#include <cstddef>

// ---------------- problem constants ----------------
#define C      64
#define CPAD   68          // padded row stride (floats) -> conflict-free LDS.128
#define NATOMS 200000
#define NPATH5 100000
#define LEN5   5
#define NPATH6 80000
#define LEN6   6
#define NPP5   4           // paths per group, L=5   (register cage: NP*L <= 20, LOCKED)
#define NPP6   3           // paths per group, L=6
#define PBLK   152         // blocks per path sub-problem (merged kernel)
#define RAT    8           // atoms per tile in zmix/atoms (proven (256,3) config)

// ---------------- scratch (device globals; zero-initialized at load) -------
// g_sum/g_cnt are restored to zero by atoms_kernel after consuming (replay safe).
// g_z5/g_z6 are fully overwritten by zmix_kernel every call.
__device__ float g_sum5[(size_t)NATOMS * C];
__device__ float g_sum6[(size_t)NATOMS * C];
__device__ float g_cnt5[NATOMS];
__device__ float g_cnt6[NATOMS];
__device__ float g_z5[(size_t)NATOMS * C];
__device__ float g_z6[(size_t)NATOMS * C];

using u64 = unsigned long long;

// ---------------- packed fp32 helpers (sm_103a FFMA2 path) ----------------
__device__ __forceinline__ void lds2(u64 &a, u64 &b, const float *p) {
    unsigned s = (unsigned)__cvta_generic_to_shared(p);
    asm volatile("ld.shared.v2.b64 {%0,%1}, [%2];" : "=l"(a), "=l"(b) : "r"(s));
}
__device__ __forceinline__ void fma2(u64 &acc, u64 a, u64 b) {
    asm volatile("fma.rn.f32x2 %0, %1, %2, %0;" : "+l"(acc) : "l"(a), "l"(b));
}
__device__ __forceinline__ float hsum2(u64 a) {
    float lo, hi;
    asm volatile("mov.b64 {%0,%1}, %2;" : "=f"(lo), "=f"(hi) : "l"(a));
    return lo + hi;
}
__device__ __forceinline__ void red4(float *p, float4 v) {
    asm volatile("red.global.add.v4.f32 [%0], {%1,%2,%3,%4};"
                 :: "l"(p), "f"(v.x), "f"(v.y), "f"(v.z), "f"(v.w) : "memory");
}
// named barrier for a 64-thread group (ids 1..8; __syncthreads owns id 0)
__device__ __forceinline__ void barg(int id) {
    asm volatile("bar.sync %0, 64;" :: "r"(id) : "memory");
}
// cp.async global->shared
__device__ __forceinline__ void cpa16(float *s, const float *g) {
    unsigned sa = (unsigned)__cvta_generic_to_shared(s);
    asm volatile("cp.async.cg.shared.global [%0], [%1], 16;" :: "r"(sa), "l"(g));
}
__device__ __forceinline__ void cpa4(float *s, const float *g) {
    unsigned sa = (unsigned)__cvta_generic_to_shared(s);
    asm volatile("cp.async.ca.shared.global [%0], [%1], 4;" :: "r"(sa), "l"(g));
}
__device__ __forceinline__ void cp_commit() {
    asm volatile("cp.async.commit_group;" ::: "memory");
}
__device__ __forceinline__ void cp_wait0() {
    asm volatile("cp.async.wait_group 0;" ::: "memory");
}
__device__ __forceinline__ void stg16_zero(float *p) {
    asm volatile("st.global.v4.f32 [%0], {%1,%1,%1,%1};" :: "l"(p), "f"(0.f) : "memory");
}

// ---------------- zmix: z = relu(x @ Wa.T + ba) for all atoms --------------
// (256,3) / RAT=8 — proven 92us configuration.
__global__ __launch_bounds__(256, 3) void zmix_kernel(
    const float *__restrict__ x,
    const float *__restrict__ Wa5, const float *__restrict__ ba5,
    const float *__restrict__ Wa6, const float *__restrict__ ba6)
{
    extern __shared__ float smem[];
    float *W5s = smem;
    float *W6s = W5s + C * CPAD;
    float *b5s = W6s + C * CPAD;
    float *b6s = b5s + C;
    float *tA  = b6s + C;             // [4 groups][RAT][C]
    float *tB  = tA + 4 * RAT * C;

    int tid = threadIdx.x;
    for (int i = tid; i < C * C; i += 256) {
        W5s[(i / C) * CPAD + (i % C)] = Wa5[i];
        W6s[(i / C) * CPAD + (i % C)] = Wa6[i];
    }
    if (tid < C) { b5s[tid] = ba5[tid]; b6s[tid] = ba6[tid]; }
    __syncthreads();

    int g = tid >> 6, t = tid & 63;
    int bid = g + 1;
    float *mA = tA + g * RAT * C;
    float *mB = tB + g * RAT * C;
    int nq = NATOMS / RAT;            // 25000 exact
    int qstride = gridDim.x * 4;
    int iters = (nq + qstride - 1) / qstride;
    int q0 = blockIdx.x * 4 + g;

    if (q0 < nq) {
        int a0 = q0 * RAT;
        for (int item = t; item < RAT * 16; item += 64) {
            int rr = item >> 4, qq = item & 15;
            cpa16(mA + rr * C + qq * 4, x + (size_t)(a0 + rr) * C + qq * 4);
        }
    }
    cp_commit();

    int pb = 0;
    for (int it = 0; it < iters; ++it) {
        int q = q0 + it * qstride;
        bool act = q < nq;
        float *mc = pb ? mB : mA;
        float *mn = pb ? mA : mB;

        cp_wait0();
        barg(bid);

        {
            int q2 = q0 + (it + 1) * qstride;
            if (q2 < nq) {
                int a0 = q2 * RAT;
                for (int item = t; item < RAT * 16; item += 64) {
                    int rr = item >> 4, qq = item & 15;
                    cpa16(mn + rr * C + qq * 4, x + (size_t)(a0 + rr) * C + qq * 4);
                }
            }
            cp_commit();
        }

        if (act) {
            int a0 = q * RAT;
            u64 a5[RAT], a6[RAT];
#pragma unroll
            for (int r = 0; r < RAT; r++) { a5[r] = 0ull; a6[r] = 0ull; }
            const float *w5r = W5s + t * CPAD;
            const float *w6r = W6s + t * CPAD;
#pragma unroll 2
            for (int c = 0; c < 16; c++) {
                u64 w50, w51, w60, w61;
                lds2(w50, w51, w5r + 4 * c);
                lds2(w60, w61, w6r + 4 * c);
#pragma unroll
                for (int r = 0; r < RAT; r++) {
                    u64 x0, x1;
                    lds2(x0, x1, mc + r * C + 4 * c);
                    fma2(a5[r], w50, x0); fma2(a5[r], w51, x1);
                    fma2(a6[r], w60, x0); fma2(a6[r], w61, x1);
                }
            }
#pragma unroll
            for (int r = 0; r < RAT; r++) {
                int a = a0 + r;
                g_z5[(size_t)a * C + t] = fmaxf(hsum2(a5[r]) + b5s[t], 0.f);
                g_z6[(size_t)a * C + t] = fmaxf(hsum2(a6[r]) + b6s[t], 0.f);
            }
        }
        pb ^= 1;
    }
}

// ---------------- conv pass: h = Wc(k=3) * vp + bias (no write) ------------
template <int L, int NP>
__device__ __forceinline__ void conv_pass(
    const float *vp, const float *w0r, const float *w1r, const float *w2r,
    float bias, float (&h)[NP][L])
{
    u64 acc[NP][L];
#pragma unroll
    for (int j = 0; j < NP; j++)
#pragma unroll
        for (int l = 0; l < L; l++) acc[j][l] = 0ull;
#pragma unroll 2
    for (int c = 0; c < 16; c++) {
        u64 wa0, wa1, wb0, wb1, wc0, wc1;
        lds2(wa0, wa1, w0r + 4 * c);
        lds2(wb0, wb1, w1r + 4 * c);
        lds2(wc0, wc1, w2r + 4 * c);
#pragma unroll
        for (int j = 0; j < NP; j++) {
            u64 a0[L], a1[L];
#pragma unroll
            for (int l = 0; l < L; l++)
                lds2(a0[l], a1[l], vp + (j * L + l) * C + 4 * c);
#pragma unroll
            for (int l = 0; l < L; l++) {
                if (l > 0)     { fma2(acc[j][l], wa0, a0[l - 1]); fma2(acc[j][l], wa1, a1[l - 1]); }
                                 fma2(acc[j][l], wb0, a0[l]);     fma2(acc[j][l], wb1, a1[l]);
                if (l < L - 1) { fma2(acc[j][l], wc0, a0[l + 1]); fma2(acc[j][l], wc1, a1[l + 1]); }
            }
        }
    }
#pragma unroll
    for (int j = 0; j < NP; j++)
#pragma unroll
        for (int l = 0; l < L; l++)
            h[j][l] = hsum2(acc[j][l]) + bias;
}

// ---------------- fused path body (gathers precomputed z; conv only) -------
template <int L, int NP>
__device__ __forceinline__ void path_body(
    float *smem, int blk, int nblk,
    const float *__restrict__ z, const float *__restrict__ xp_in,
    const int *__restrict__ row,
    const float *__restrict__ Wc, const float *__restrict__ bc,
    float *__restrict__ xp_out, int P, float *sum, float *cnt)
{
    constexpr int NV = NP * L;
    constexpr int GI = (NV * 16 + 63) / 64;   // float4 items per thread

    float *Wc_s = smem;                      // 6*C*CPAD
    float *bc_s = Wc_s + 6 * C * CPAD;       // 2*C
    float *vA   = bc_s + 2 * C;              // 8*NV*C (buffer A)
    float *vB   = vA + 8 * NV * C;           // 8*NV*C (buffer B)
    int   *rows = (int *)(vB + 8 * NV * C);  // 8*2*NV

    int tid = threadIdx.x;
    for (int i = tid; i < 6 * C * C; i += 512) {
        int m = i / (C * C);
        int r = i - m * C * C;
        int ci = r / C, co = r - ci * C;
        Wc_s[(m * C + co) * CPAD + ci] = Wc[i];
    }
    if (tid < 2 * C) bc_s[tid] = bc[tid];
    __syncthreads();

    int g = tid >> 6, t = tid & 63;
    int bid = g + 1;
    float *vpa = vA + g * NV * C;
    float *vpb = vB + g * NV * C;
    int *rp0 = rows + g * 2 * NV;
    int *rp1 = rp0 + NV;
    int NG = nblk * 8;
    int iters = (P + NG * NP - 1) / (NG * NP);
    int G = blk * 8 + g;

    // prologue: rows_0 -> rp0; cp.async gather_0 (z rows) -> vpa
    if (t < NV) {
        int j = t / L, l = t - j * L;
        int p = G * NP + j;
        rp0[t] = (p < P) ? row[p * L + l] : 0;
    }
    barg(bid);
    for (int item = t; item < NV * 16; item += 64) {
        int r = item >> 4, q = item & 15;
        cpa16(vpa + r * C + q * 4, z + (size_t)rp0[r] * C + q * 4);
    }
    cp_commit();

    int pb = 0;
    for (int it = 0; it < iters; ++it) {
        int pbase = (it * NG + G) * NP;
        int pnext = ((it + 1) * NG + G) * NP;
        float *vp = pb ? vpb : vpa;
        float *vn = pb ? vpa : vpb;
        int *rp_cur = pb ? rp1 : rp0;
        int *rp_nxt = pb ? rp0 : rp1;

        // phase 1: issue rows_{i+1} + xp_in loads (float4 item layout); wait
        int rnext = 0;
        if (t < NV) {
            int j = t / L, l = t - j * L;
            int p = pnext + j;
            if (p < P) rnext = row[p * L + l];
        }
        float4 xi[GI];
#pragma unroll
        for (int ii = 0; ii < GI; ii++) {
            int item = t + 64 * ii;
            xi[ii] = make_float4(0.f, 0.f, 0.f, 0.f);
            if (item < NV * 16) {
                int r = item >> 4, q = item & 15;
                int j = r / L;
                if (pbase + j < P)
                    xi[ii] = ((const float4 *)(xp_in + (size_t)(pbase + j) * L * C))
                                 [(r - j * L) * 16 + q];
            }
        }
        cp_wait0();
        barg(bid);  // gathered z in vp visible to whole group

        // phase 2: v = z + xp_in  (float4 item layout); stash rows_{i+1}
#pragma unroll
        for (int ii = 0; ii < GI; ii++) {
            int item = t + 64 * ii;
            if (item < NV * 16) {
                float4 v = ((float4 *)vp)[item];
                v.x += xi[ii].x; v.y += xi[ii].y; v.z += xi[ii].z; v.w += xi[ii].w;
                ((float4 *)vp)[item] = v;
            }
        }
        if (t < NV) rp_nxt[t] = rnext;
        barg(bid);

        // phase 2.5: issue gather_{i+1} into vn NOW (rp_nxt valid after barg;
        // vn is free) -> latency hides under BOTH conv passes.
        for (int item = t; item < NV * 16; item += 64) {
            int r = item >> 4, q = item & 15;
            cpa16(vn + r * C + q * 4, z + (size_t)rp_nxt[r] * C + q * 4);
        }
        cp_commit();

        // phase 3: conv depth 0
        float h[NP][L];
        conv_pass<L, NP>(vp, Wc_s + (0 * C + t) * CPAD, Wc_s + (1 * C + t) * CPAD,
                         Wc_s + (2 * C + t) * CPAD, bc_s[t], h);
        barg(bid);
#pragma unroll
        for (int j = 0; j < NP; j++)
#pragma unroll
            for (int l = 0; l < L; l++)
                vp[(j * L + l) * C + t] += fmaxf(h[j][l], 0.f);
        barg(bid);

        // phase 4: conv depth 1
        conv_pass<L, NP>(vp, Wc_s + (3 * C + t) * CPAD, Wc_s + (4 * C + t) * CPAD,
                         Wc_s + (5 * C + t) * CPAD, bc_s[C + t], h);
        barg(bid);
#pragma unroll
        for (int j = 0; j < NP; j++)
#pragma unroll
            for (int l = 0; l < L; l++)
                vp[(j * L + l) * C + t] += fmaxf(h[j][l], 0.f);
        barg(bid);

        // phase 5: write xp_out + scatter into atom accumulators.
        // (no trailing barrier: vp/rp_cur untouched until after next phase-1 barg)
        for (int item = t; item < NV * 16; item += 64) {
            int r = item >> 4, q = item & 15;
            int j = r / L;
            if (pbase + j < P) {
                float4 v = ((float4 *)vp)[r * 16 + q];
                ((float4 *)(xp_out + (size_t)(pbase + j) * L * C))[(r - j * L) * 16 + q] = v;
                red4(sum + (size_t)rp_cur[r] * C + q * 4, v);
            }
        }
        if (t < NV && pbase + t / L < P)
            atomicAdd(&cnt[rp_cur[t]], 1.0f);
        pb ^= 1;
    }
}

// ---------------- merged path kernel ----------------
__global__ __launch_bounds__(512, 1) void paths_kernel(
    const float *__restrict__ xp5, const float *__restrict__ xp6,
    const int *__restrict__ row5, const int *__restrict__ row6,
    const float *__restrict__ Wc5, const float *__restrict__ bc5,
    const float *__restrict__ Wc6, const float *__restrict__ bc6,
    float *__restrict__ xp5_out, float *__restrict__ xp6_out)
{
    extern __shared__ float smem[];
    if (blockIdx.x < PBLK)
        path_body<LEN5, NPP5>(smem, blockIdx.x, PBLK, g_z5, xp5, row5,
                              Wc5, bc5, xp5_out, NPATH5, g_sum5, g_cnt5);
    else
        path_body<LEN6, NPP6>(smem, blockIdx.x - PBLK, PBLK, g_z6, xp6, row6,
                              Wc6, bc6, xp6_out, NPATH6, g_sum6, g_cnt6);
}

// ---------------- atom kernel (cp.async pipelined, self-cleaning) ----------
// (256,3) / RAT=8 — proven configuration; zero-restore after compute issue.
__global__ __launch_bounds__(256, 3) void atoms_kernel(
    const float *__restrict__ x,
    const float *__restrict__ Wp5, const float *__restrict__ bp5,
    const float *__restrict__ Wp6, const float *__restrict__ bp6,
    float *__restrict__ xout)
{
    extern __shared__ float smem[];
    float *W5s = smem;
    float *W6s = W5s + C * CPAD;
    float *b5s = W6s + C * CPAD;
    float *b6s = b5s + C;
    float *msA = b6s + C;                 // [4 groups][2*RAT][C]
    float *msB = msA + 4 * 2 * RAT * C;
    float *cnA = msB + 4 * 2 * RAT * C;   // [4 groups][2*RAT]
    float *cnB = cnA + 4 * 2 * RAT;

    int tid = threadIdx.x;
    for (int i = tid; i < C * C; i += 256) {
        W5s[(i / C) * CPAD + (i % C)] = Wp5[i];
        W6s[(i / C) * CPAD + (i % C)] = Wp6[i];
    }
    if (tid < C) { b5s[tid] = bp5[tid]; b6s[tid] = bp6[tid]; }
    __syncthreads();

    int g = tid >> 6, t = tid & 63;
    int bid = g + 1;
    float *mA = msA + g * 2 * RAT * C;
    float *mB = msB + g * 2 * RAT * C;
    float *cA = cnA + g * 2 * RAT;
    float *cB = cnB + g * 2 * RAT;
    int nq = NATOMS / RAT;                // 25000 exact
    int qstride = gridDim.x * 4;
    int iters = (nq + qstride - 1) / qstride;
    int q0 = blockIdx.x * 4 + g;

    if (q0 < nq) {
        int a0 = q0 * RAT;
        for (int item = t; item < 2 * RAT * 16; item += 64) {
            int rr = item >> 4, qq = item & 15;
            const float *src = (rr < RAT)
                ? g_sum5 + (size_t)(a0 + rr) * C + qq * 4
                : g_sum6 + (size_t)(a0 + rr - RAT) * C + qq * 4;
            cpa16(mA + rr * C + qq * 4, src);
        }
        if (t < 2 * RAT)
            cpa4(cA + t, (t < RAT) ? g_cnt5 + a0 + t : g_cnt6 + a0 + t - RAT);
    }
    cp_commit();

    int pb = 0;
    for (int it = 0; it < iters; ++it) {
        int q = q0 + it * qstride;
        bool act = q < nq;
        float *mc = pb ? mB : mA;
        float *mn = pb ? mA : mB;
        float *cc2 = pb ? cB : cA;
        float *cn2 = pb ? cA : cB;

        cp_wait0();
        barg(bid);

        {
            int q2 = q0 + (it + 1) * qstride;
            if (q2 < nq) {
                int a0 = q2 * RAT;
                for (int item = t; item < 2 * RAT * 16; item += 64) {
                    int rr = item >> 4, qq = item & 15;
                    const float *src = (rr < RAT)
                        ? g_sum5 + (size_t)(a0 + rr) * C + qq * 4
                        : g_sum6 + (size_t)(a0 + rr - RAT) * C + qq * 4;
                    cpa16(mn + rr * C + qq * 4, src);
                }
                if (t < 2 * RAT)
                    cpa4(cn2 + t, (t < RAT) ? g_cnt5 + a0 + t : g_cnt6 + a0 + t - RAT);
            }
            cp_commit();
        }

        if (act) {
            int a0 = q * RAT;
            float c5[RAT], c6[RAT], xv[RAT];
#pragma unroll
            for (int r = 0; r < RAT; r++) {
                c5[r] = cc2[r];
                c6[r] = cc2[RAT + r];
                xv[r] = x[(size_t)(a0 + r) * C + t];
            }
            u64 a5[RAT], a6[RAT];
#pragma unroll
            for (int r = 0; r < RAT; r++) { a5[r] = 0ull; a6[r] = 0ull; }
            const float *w5r = W5s + t * CPAD;
            const float *w6r = W6s + t * CPAD;
#pragma unroll 2
            for (int c = 0; c < 16; c++) {
                u64 w50, w51, w60, w61;
                lds2(w50, w51, w5r + 4 * c);
                lds2(w60, w61, w6r + 4 * c);
#pragma unroll
                for (int r = 0; r < RAT; r++) {
                    u64 x0, x1;
                    lds2(x0, x1, mc + r * C + 4 * c);
                    fma2(a5[r], w50, x0); fma2(a5[r], w51, x1);
                    u64 y0, y1;
                    lds2(y0, y1, mc + (RAT + r) * C + 4 * c);
                    fma2(a6[r], w60, y0); fma2(a6[r], w61, y1);
                }
            }
#pragma unroll
            for (int r = 0; r < RAT; r++) {
                int a = a0 + r;
                float v = xv[r]
                        + fmaxf(hsum2(a5[r]) / fmaxf(c5[r], 1.f) + b5s[t], 0.f)
                        + fmaxf(hsum2(a6[r]) / fmaxf(c6[r], 1.f) + b6s[t], 0.f);
                xout[(size_t)a * C + t] = v;
            }

            // restore consumed global regions to zero (after compute issue)
            for (int item = t; item < 2 * RAT * 16; item += 64) {
                int rr = item >> 4, qq = item & 15;
                float *dst = (rr < RAT)
                    ? g_sum5 + (size_t)(a0 + rr) * C + qq * 4
                    : g_sum6 + (size_t)(a0 + rr - RAT) * C + qq * 4;
                stg16_zero(dst);
            }
            if (t < 2 * RAT)
                *((t < RAT) ? g_cnt5 + a0 + t : g_cnt6 + a0 + t - RAT) = 0.f;
        }
        pb ^= 1;
    }
}

// ---------------- launch ----------------
extern "C" void kernel_launch(void *const *d_in, const int *in_sizes, int n_in,
                              void *d_out, int out_size)
{
    const float *x    = (const float *)d_in[0];
    const float *xp5  = (const float *)d_in[1];
    const float *xp6  = (const float *)d_in[2];
    const int   *row5 = (const int *)d_in[3];
    // d_in[4] = col5 (identity arange), unused
    const int   *row6 = (const int *)d_in[5];
    // d_in[6] = col6 (identity arange), unused
    const float *Wa5 = (const float *)d_in[7];
    const float *ba5 = (const float *)d_in[8];
    const float *Wa6 = (const float *)d_in[9];
    const float *ba6 = (const float *)d_in[10];
    const float *Wp5 = (const float *)d_in[11];
    const float *bp5 = (const float *)d_in[12];
    const float *Wp6 = (const float *)d_in[13];
    const float *bp6 = (const float *)d_in[14];
    const float *Wc5 = (const float *)d_in[15];
    const float *bc5 = (const float *)d_in[16];
    const float *Wc6 = (const float *)d_in[17];
    const float *bc6 = (const float *)d_in[18];

    float *x_out   = (float *)d_out;
    float *xp5_out = x_out + (size_t)NATOMS * C;
    float *xp6_out = xp5_out + (size_t)NPATH5 * LEN5 * C;

    constexpr int NV5 = NPP5 * LEN5;   // 20
    constexpr int NV6 = NPP6 * LEN6;   // 18
    constexpr int smem_wts = (6 * C * CPAD + 2 * C) * 4;
    constexpr int smem5 = smem_wts + (2 * 8 * NV5 * C) * 4 + (8 * 2 * NV5) * 4;
    constexpr int smem6 = smem_wts + (2 * 8 * NV6 * C) * 4 + (8 * 2 * NV6) * 4;
    constexpr int smemP = (smem5 > smem6) ? smem5 : smem6;
    constexpr int smemA = (2 * C * CPAD + 2 * C + 2 * 4 * 2 * RAT * C + 2 * 4 * 2 * RAT) * 4;
    constexpr int smemZ = (2 * C * CPAD + 2 * C + 2 * 4 * RAT * C) * 4;

    static_assert(smemP < 227 * 1024, "path smem");
    static_assert(smemA < 76 * 1024, "atoms smem (3 CTAs/SM)");
    static_assert(smemZ < 76 * 1024, "zmix smem (3 CTAs/SM)");

    cudaFuncSetAttribute((const void *)paths_kernel,
                         cudaFuncAttributeMaxDynamicSharedMemorySize, smemP);
    cudaFuncSetAttribute((const void *)atoms_kernel,
                         cudaFuncAttributeMaxDynamicSharedMemorySize, smemA);
    cudaFuncSetAttribute((const void *)zmix_kernel,
                         cudaFuncAttributeMaxDynamicSharedMemorySize, smemZ);

    zmix_kernel<<<456, 256, smemZ>>>(x, Wa5, ba5, Wa6, ba6);

    paths_kernel<<<2 * PBLK, 512, smemP>>>(xp5, xp6, row5, row6,
                                           Wc5, bc5, Wc6, bc6,
                                           xp5_out, xp6_out);

    atoms_kernel<<<456, 256, smemA>>>(x, Wp5, bp5, Wp6, bp6, x_out);
}

// round 16
// speedup vs baseline: 1.0341x; 1.0281x over previous
#include <cuda_runtime.h>
#include <cstddef>

// ---------------- problem constants ----------------
#define C      64
#define CPAD   68          // padded row stride (floats) -> conflict-free LDS.128
#define NATOMS 200000
#define NPATH5 100000
#define LEN5   5
#define NPATH6 80000
#define LEN6   6
#define NPP5   4           // paths per group, L=5   (register cage: NP*L <= 20, LOCKED)
#define NPP6   3           // paths per group, L=6
#define PBLK   152         // blocks per path sub-problem (merged kernel)
#define RAT    8           // atoms per tile in zmix/atoms (proven (256,3) config)

// ---------------- scratch (device globals; zero-initialized at load) -------
// g_sum/g_cnt are restored to zero by atoms_kernel after consuming (replay safe).
// g_z5/g_z6 are fully overwritten by zmix_kernel every call.
__device__ float g_sum5[(size_t)NATOMS * C];
__device__ float g_sum6[(size_t)NATOMS * C];
__device__ float g_cnt5[NATOMS];
__device__ float g_cnt6[NATOMS];
__device__ float g_z5[(size_t)NATOMS * C];
__device__ float g_z6[(size_t)NATOMS * C];

using u64 = unsigned long long;

// ---------------- packed fp32 helpers (sm_103a FFMA2 path) ----------------
__device__ __forceinline__ void lds2(u64 &a, u64 &b, const float *p) {
    unsigned s = (unsigned)__cvta_generic_to_shared(p);
    asm volatile("ld.shared.v2.b64 {%0,%1}, [%2];" : "=l"(a), "=l"(b) : "r"(s));
}
__device__ __forceinline__ void fma2(u64 &acc, u64 a, u64 b) {
    asm volatile("fma.rn.f32x2 %0, %1, %2, %0;" : "+l"(acc) : "l"(a), "l"(b));
}
__device__ __forceinline__ float hsum2(u64 a) {
    float lo, hi;
    asm volatile("mov.b64 {%0,%1}, %2;" : "=f"(lo), "=f"(hi) : "l"(a));
    return lo + hi;
}
__device__ __forceinline__ void red4(float *p, float4 v) {
    asm volatile("red.global.add.v4.f32 [%0], {%1,%2,%3,%4};"
                 :: "l"(p), "f"(v.x), "f"(v.y), "f"(v.z), "f"(v.w) : "memory");
}
// named barrier for a 64-thread group (ids 1..8; __syncthreads owns id 0)
__device__ __forceinline__ void barg(int id) {
    asm volatile("bar.sync %0, 64;" :: "r"(id) : "memory");
}
// cp.async global->shared
__device__ __forceinline__ void cpa16(float *s, const float *g) {
    unsigned sa = (unsigned)__cvta_generic_to_shared(s);
    asm volatile("cp.async.cg.shared.global [%0], [%1], 16;" :: "r"(sa), "l"(g));
}
__device__ __forceinline__ void cp_commit() {
    asm volatile("cp.async.commit_group;" ::: "memory");
}
__device__ __forceinline__ void cp_wait0() {
    asm volatile("cp.async.wait_group 0;" ::: "memory");
}
__device__ __forceinline__ void stg16_zero(float *p) {
    asm volatile("st.global.v4.f32 [%0], {%1,%1,%1,%1};" :: "l"(p), "f"(0.f) : "memory");
}

// ---------------- zmix: z = relu(x @ Wa.T + ba) for all atoms --------------
// (256,3) / RAT=8 — proven 92us configuration (exact R11 source).
__global__ __launch_bounds__(256, 3) void zmix_kernel(
    const float *__restrict__ x,
    const float *__restrict__ Wa5, const float *__restrict__ ba5,
    const float *__restrict__ Wa6, const float *__restrict__ ba6)
{
    extern __shared__ float smem[];
    float *W5s = smem;
    float *W6s = W5s + C * CPAD;
    float *b5s = W6s + C * CPAD;
    float *b6s = b5s + C;
    float *tA  = b6s + C;             // [4 groups][RAT][C]
    float *tB  = tA + 4 * RAT * C;

    int tid = threadIdx.x;
    for (int i = tid; i < C * C; i += 256) {
        W5s[(i / C) * CPAD + (i % C)] = Wa5[i];
        W6s[(i / C) * CPAD + (i % C)] = Wa6[i];
    }
    if (tid < C) { b5s[tid] = ba5[tid]; b6s[tid] = ba6[tid]; }
    __syncthreads();

    int g = tid >> 6, t = tid & 63;
    int bid = g + 1;
    float *mA = tA + g * RAT * C;
    float *mB = tB + g * RAT * C;
    int nq = NATOMS / RAT;            // 25000 exact
    int qstride = gridDim.x * 4;
    int iters = (nq + qstride - 1) / qstride;
    int q0 = blockIdx.x * 4 + g;

    if (q0 < nq) {
        int a0 = q0 * RAT;
        for (int item = t; item < RAT * 16; item += 64) {
            int rr = item >> 4, qq = item & 15;
            cpa16(mA + rr * C + qq * 4, x + (size_t)(a0 + rr) * C + qq * 4);
        }
    }
    cp_commit();

    int pb = 0;
    for (int it = 0; it < iters; ++it) {
        int q = q0 + it * qstride;
        bool act = q < nq;
        float *mc = pb ? mB : mA;
        float *mn = pb ? mA : mB;

        cp_wait0();
        barg(bid);

        {
            int q2 = q0 + (it + 1) * qstride;
            if (q2 < nq) {
                int a0 = q2 * RAT;
                for (int item = t; item < RAT * 16; item += 64) {
                    int rr = item >> 4, qq = item & 15;
                    cpa16(mn + rr * C + qq * 4, x + (size_t)(a0 + rr) * C + qq * 4);
                }
            }
            cp_commit();
        }

        if (act) {
            int a0 = q * RAT;
            u64 a5[RAT], a6[RAT];
#pragma unroll
            for (int r = 0; r < RAT; r++) { a5[r] = 0ull; a6[r] = 0ull; }
            const float *w5r = W5s + t * CPAD;
            const float *w6r = W6s + t * CPAD;
#pragma unroll 2
            for (int c = 0; c < 16; c++) {
                u64 w50, w51, w60, w61;
                lds2(w50, w51, w5r + 4 * c);
                lds2(w60, w61, w6r + 4 * c);
#pragma unroll
                for (int r = 0; r < RAT; r++) {
                    u64 x0, x1;
                    lds2(x0, x1, mc + r * C + 4 * c);
                    fma2(a5[r], w50, x0); fma2(a5[r], w51, x1);
                    fma2(a6[r], w60, x0); fma2(a6[r], w61, x1);
                }
            }
#pragma unroll
            for (int r = 0; r < RAT; r++) {
                int a = a0 + r;
                g_z5[(size_t)a * C + t] = fmaxf(hsum2(a5[r]) + b5s[t], 0.f);
                g_z6[(size_t)a * C + t] = fmaxf(hsum2(a6[r]) + b6s[t], 0.f);
            }
        }
        pb ^= 1;
    }
}

// ---------------- conv pass: h = Wc(k=3) * vp + bias (no write) ------------
template <int L, int NP>
__device__ __forceinline__ void conv_pass(
    const float *vp, const float *w0r, const float *w1r, const float *w2r,
    float bias, float (&h)[NP][L])
{
    u64 acc[NP][L];
#pragma unroll
    for (int j = 0; j < NP; j++)
#pragma unroll
        for (int l = 0; l < L; l++) acc[j][l] = 0ull;
#pragma unroll 2
    for (int c = 0; c < 16; c++) {
        u64 wa0, wa1, wb0, wb1, wc0, wc1;
        lds2(wa0, wa1, w0r + 4 * c);
        lds2(wb0, wb1, w1r + 4 * c);
        lds2(wc0, wc1, w2r + 4 * c);
#pragma unroll
        for (int j = 0; j < NP; j++) {
            u64 a0[L], a1[L];
#pragma unroll
            for (int l = 0; l < L; l++)
                lds2(a0[l], a1[l], vp + (j * L + l) * C + 4 * c);
#pragma unroll
            for (int l = 0; l < L; l++) {
                if (l > 0)     { fma2(acc[j][l], wa0, a0[l - 1]); fma2(acc[j][l], wa1, a1[l - 1]); }
                                 fma2(acc[j][l], wb0, a0[l]);     fma2(acc[j][l], wb1, a1[l]);
                if (l < L - 1) { fma2(acc[j][l], wc0, a0[l + 1]); fma2(acc[j][l], wc1, a1[l + 1]); }
            }
        }
    }
#pragma unroll
    for (int j = 0; j < NP; j++)
#pragma unroll
        for (int l = 0; l < L; l++)
            h[j][l] = hsum2(acc[j][l]) + bias;
}

// ---------------- fused path body (exact R11 structure + tail skip) --------
template <int L, int NP>
__device__ __forceinline__ void path_body(
    float *smem, int blk, int nblk,
    const float *__restrict__ z, const float *__restrict__ xp_in,
    const int *__restrict__ row,
    const float *__restrict__ Wc, const float *__restrict__ bc,
    float *__restrict__ xp_out, int P, float *sum, float *cnt)
{
    constexpr int NV = NP * L;

    float *Wc_s = smem;                      // 6*C*CPAD
    float *bc_s = Wc_s + 6 * C * CPAD;       // 2*C
    float *vA   = bc_s + 2 * C;              // 8*NV*C (buffer A)
    float *vB   = vA + 8 * NV * C;           // 8*NV*C (buffer B)
    int   *rows = (int *)(vB + 8 * NV * C);  // 8*2*NV

    int tid = threadIdx.x;
    for (int i = tid; i < 6 * C * C; i += 512) {
        int m = i / (C * C);
        int r = i - m * C * C;
        int ci = r / C, co = r - ci * C;
        Wc_s[(m * C + co) * CPAD + ci] = Wc[i];
    }
    if (tid < 2 * C) bc_s[tid] = bc[tid];
    __syncthreads();

    int g = tid >> 6, t = tid & 63;
    int bid = g + 1;
    float *vpa = vA + g * NV * C;
    float *vpb = vB + g * NV * C;
    int *rp0 = rows + g * 2 * NV;
    int *rp1 = rp0 + NV;
    int NG = nblk * 8;
    int iters = (P + NG * NP - 1) / (NG * NP);
    int G = blk * 8 + g;

    // prologue: rows_0 -> rp0; cp.async gather_0 (z rows) -> vpa
    if (t < NV) {
        int j = t / L, l = t - j * L;
        int p = G * NP + j;
        rp0[t] = (p < P) ? row[p * L + l] : 0;
    }
    barg(bid);
    for (int item = t; item < NV * 16; item += 64) {
        int r = item >> 4, q = item & 15;
        cpa16(vpa + r * C + q * 4, z + (size_t)rp0[r] * C + q * 4);
    }
    cp_commit();

    int pb = 0;
    for (int it = 0; it < iters; ++it) {
        int pbase = (it * NG + G) * NP;
        // group-uniform tail skip: once this group's range is past P it stays
        // past P (pbase monotone in it); barg is group-local so skipping the
        // whole body is safe. Trailing cp_wait0 after the loop drains the
        // last prefetch.
        if (pbase >= P) { pb ^= 1; continue; }

        int pnext = ((it + 1) * NG + G) * NP;
        float *vp = pb ? vpb : vpa;
        float *vn = pb ? vpa : vpb;
        int *rp_cur = pb ? rp1 : rp0;
        int *rp_nxt = pb ? rp0 : rp1;

        // phase 1: issue rows_{i+1} + xp_in loads; wait gather; sync
        int rnext = 0;
        if (t < NV) {
            int j = t / L, l = t - j * L;
            int p = pnext + j;
            if (p < P) rnext = row[p * L + l];
        }
        float xr[NP][L];
#pragma unroll
        for (int j = 0; j < NP; j++) {
            int p = pbase + j;
#pragma unroll
            for (int l = 0; l < L; l++)
                xr[j][l] = (p < P) ? xp_in[(size_t)p * L * C + l * C + t] : 0.f;
        }
        cp_wait0();
        barg(bid);  // gathered z in vp visible to whole group

        // phase 2: v = z + xp_in  (elementwise, each thread owns column t)
#pragma unroll
        for (int j = 0; j < NP; j++)
#pragma unroll
            for (int l = 0; l < L; l++)
                vp[(j * L + l) * C + t] += xr[j][l];
        if (t < NV) rp_nxt[t] = rnext;
        barg(bid);

        // phase 3: conv depth 0
        float h[NP][L];
        conv_pass<L, NP>(vp, Wc_s + (0 * C + t) * CPAD, Wc_s + (1 * C + t) * CPAD,
                         Wc_s + (2 * C + t) * CPAD, bc_s[t], h);
        barg(bid);
#pragma unroll
        for (int j = 0; j < NP; j++)
#pragma unroll
            for (int l = 0; l < L; l++)
                vp[(j * L + l) * C + t] += fmaxf(h[j][l], 0.f);

        // phase 3.5: issue gather_{i+1} into vn (register-free; hides under d1)
        for (int item = t; item < NV * 16; item += 64) {
            int r = item >> 4, q = item & 15;
            cpa16(vn + r * C + q * 4, z + (size_t)rp_nxt[r] * C + q * 4);
        }
        cp_commit();
        barg(bid);

        // phase 4: conv depth 1
        conv_pass<L, NP>(vp, Wc_s + (3 * C + t) * CPAD, Wc_s + (4 * C + t) * CPAD,
                         Wc_s + (5 * C + t) * CPAD, bc_s[C + t], h);
        barg(bid);
#pragma unroll
        for (int j = 0; j < NP; j++)
#pragma unroll
            for (int l = 0; l < L; l++)
                vp[(j * L + l) * C + t] += fmaxf(h[j][l], 0.f);
        barg(bid);

        // phase 5: write xp_out + scatter into atom accumulators.
        // (no trailing barrier: vp/rp_cur untouched until after next phase-1 barg)
        for (int item = t; item < NV * 16; item += 64) {
            int r = item >> 4, q = item & 15;
            int j = r / L;
            if (pbase + j < P) {
                float4 v = ((float4 *)vp)[r * 16 + q];
                ((float4 *)(xp_out + (size_t)(pbase + j) * L * C))[(r - j * L) * 16 + q] = v;
                red4(sum + (size_t)rp_cur[r] * C + q * 4, v);
            }
        }
        if (t < NV && pbase + t / L < P)
            atomicAdd(&cnt[rp_cur[t]], 1.0f);
        pb ^= 1;
    }
    cp_wait0();   // drain last prefetch before CTA exit
}

// ---------------- merged path kernel ----------------
__global__ __launch_bounds__(512, 1) void paths_kernel(
    const float *__restrict__ xp5, const float *__restrict__ xp6,
    const int *__restrict__ row5, const int *__restrict__ row6,
    const float *__restrict__ Wc5, const float *__restrict__ bc5,
    const float *__restrict__ Wc6, const float *__restrict__ bc6,
    float *__restrict__ xp5_out, float *__restrict__ xp6_out)
{
    extern __shared__ float smem[];
    if (blockIdx.x < PBLK)
        path_body<LEN5, NPP5>(smem, blockIdx.x, PBLK, g_z5, xp5, row5,
                              Wc5, bc5, xp5_out, NPATH5, g_sum5, g_cnt5);
    else
        path_body<LEN6, NPP6>(smem, blockIdx.x - PBLK, PBLK, g_z6, xp6, row6,
                              Wc6, bc6, xp6_out, NPATH6, g_sum6, g_cnt6);
}

// ---------------- atom kernel (cp.async pipelined, self-cleaning) ----------
// (256,3) / RAT=8; counts via latency-hidden LDG; zero-restore after GEMM.
__global__ __launch_bounds__(256, 3) void atoms_kernel(
    const float *__restrict__ x,
    const float *__restrict__ Wp5, const float *__restrict__ bp5,
    const float *__restrict__ Wp6, const float *__restrict__ bp6,
    float *__restrict__ xout)
{
    extern __shared__ float smem[];
    float *W5s = smem;
    float *W6s = W5s + C * CPAD;
    float *b5s = W6s + C * CPAD;
    float *b6s = b5s + C;
    float *msA = b6s + C;                 // [4 groups][2*RAT][C]
    float *msB = msA + 4 * 2 * RAT * C;

    int tid = threadIdx.x;
    for (int i = tid; i < C * C; i += 256) {
        W5s[(i / C) * CPAD + (i % C)] = Wp5[i];
        W6s[(i / C) * CPAD + (i % C)] = Wp6[i];
    }
    if (tid < C) { b5s[tid] = bp5[tid]; b6s[tid] = bp6[tid]; }
    __syncthreads();

    int g = tid >> 6, t = tid & 63;
    int bid = g + 1;
    float *mA = msA + g * 2 * RAT * C;
    float *mB = msB + g * 2 * RAT * C;
    int nq = NATOMS / RAT;                // 25000 exact
    int qstride = gridDim.x * 4;
    int iters = (nq + qstride - 1) / qstride;
    int q0 = blockIdx.x * 4 + g;

    if (q0 < nq) {
        int a0 = q0 * RAT;
        for (int item = t; item < 2 * RAT * 16; item += 64) {
            int rr = item >> 4, qq = item & 15;
            const float *src = (rr < RAT)
                ? g_sum5 + (size_t)(a0 + rr) * C + qq * 4
                : g_sum6 + (size_t)(a0 + rr - RAT) * C + qq * 4;
            cpa16(mA + rr * C + qq * 4, src);
        }
    }
    cp_commit();

    int pb = 0;
    for (int it = 0; it < iters; ++it) {
        int q = q0 + it * qstride;
        bool act = q < nq;
        float *mc = pb ? mB : mA;
        float *mn = pb ? mA : mB;

        cp_wait0();
        barg(bid);

        {
            int q2 = q0 + (it + 1) * qstride;
            if (q2 < nq) {
                int a0 = q2 * RAT;
                for (int item = t; item < 2 * RAT * 16; item += 64) {
                    int rr = item >> 4, qq = item & 15;
                    const float *src = (rr < RAT)
                        ? g_sum5 + (size_t)(a0 + rr) * C + qq * 4
                        : g_sum6 + (size_t)(a0 + rr - RAT) * C + qq * 4;
                    cpa16(mn + rr * C + qq * 4, src);
                }
            }
            cp_commit();
        }

        if (act) {
            int a0 = q * RAT;
            // issue latency-hidden loads first: counts + x rows (used after GEMM)
            float c5[RAT], c6[RAT], xv[RAT];
#pragma unroll
            for (int r = 0; r < RAT; r++) {
                c5[r] = g_cnt5[a0 + r];
                c6[r] = g_cnt6[a0 + r];
                xv[r] = x[(size_t)(a0 + r) * C + t];
            }
            u64 a5[RAT], a6[RAT];
#pragma unroll
            for (int r = 0; r < RAT; r++) { a5[r] = 0ull; a6[r] = 0ull; }
            const float *w5r = W5s + t * CPAD;
            const float *w6r = W6s + t * CPAD;
#pragma unroll 2
            for (int c = 0; c < 16; c++) {
                u64 w50, w51, w60, w61;
                lds2(w50, w51, w5r + 4 * c);
                lds2(w60, w61, w6r + 4 * c);
#pragma unroll
                for (int r = 0; r < RAT; r++) {
                    u64 x0, x1;
                    lds2(x0, x1, mc + r * C + 4 * c);
                    fma2(a5[r], w50, x0); fma2(a5[r], w51, x1);
                    u64 y0, y1;
                    lds2(y0, y1, mc + (RAT + r) * C + 4 * c);
                    fma2(a6[r], w60, y0); fma2(a6[r], w61, y1);
                }
            }
#pragma unroll
            for (int r = 0; r < RAT; r++) {
                int a = a0 + r;
                float v = xv[r]
                        + fmaxf(hsum2(a5[r]) / fmaxf(c5[r], 1.f) + b5s[t], 0.f)
                        + fmaxf(hsum2(a6[r]) / fmaxf(c6[r], 1.f) + b6s[t], 0.f);
                xout[(size_t)a * C + t] = v;
            }

            // restore consumed global regions to zero (after compute issue)
            for (int item = t; item < 2 * RAT * 16; item += 64) {
                int rr = item >> 4, qq = item & 15;
                float *dst = (rr < RAT)
                    ? g_sum5 + (size_t)(a0 + rr) * C + qq * 4
                    : g_sum6 + (size_t)(a0 + rr - RAT) * C + qq * 4;
                stg16_zero(dst);
            }
            if (t < 2 * RAT)
                *((t < RAT) ? g_cnt5 + a0 + t : g_cnt6 + a0 + t - RAT) = 0.f;
        }
        pb ^= 1;
    }
}

// ---------------- launch ----------------
extern "C" void kernel_launch(void *const *d_in, const int *in_sizes, int n_in,
                              void *d_out, int out_size)
{
    const float *x    = (const float *)d_in[0];
    const float *xp5  = (const float *)d_in[1];
    const float *xp6  = (const float *)d_in[2];
    const int   *row5 = (const int *)d_in[3];
    // d_in[4] = col5 (identity arange), unused
    const int   *row6 = (const int *)d_in[5];
    // d_in[6] = col6 (identity arange), unused
    const float *Wa5 = (const float *)d_in[7];
    const float *ba5 = (const float *)d_in[8];
    const float *Wa6 = (const float *)d_in[9];
    const float *ba6 = (const float *)d_in[10];
    const float *Wp5 = (const float *)d_in[11];
    const float *bp5 = (const float *)d_in[12];
    const float *Wp6 = (const float *)d_in[13];
    const float *bp6 = (const float *)d_in[14];
    const float *Wc5 = (const float *)d_in[15];
    const float *bc5 = (const float *)d_in[16];
    const float *Wc6 = (const float *)d_in[17];
    const float *bc6 = (const float *)d_in[18];

    float *x_out   = (float *)d_out;
    float *xp5_out = x_out + (size_t)NATOMS * C;
    float *xp6_out = xp5_out + (size_t)NPATH5 * LEN5 * C;

    constexpr int NV5 = NPP5 * LEN5;   // 20
    constexpr int NV6 = NPP6 * LEN6;   // 18
    constexpr int smem_wts = (6 * C * CPAD + 2 * C) * 4;
    constexpr int smem5 = smem_wts + (2 * 8 * NV5 * C) * 4 + (8 * 2 * NV5) * 4;
    constexpr int smem6 = smem_wts + (2 * 8 * NV6 * C) * 4 + (8 * 2 * NV6) * 4;
    constexpr int smemP = (smem5 > smem6) ? smem5 : smem6;
    constexpr int smemA = (2 * C * CPAD + 2 * C + 2 * 4 * 2 * RAT * C) * 4;
    constexpr int smemZ = (2 * C * CPAD + 2 * C + 2 * 4 * RAT * C) * 4;

    static_assert(smemP < 227 * 1024, "path smem");
    static_assert(smemA < 76 * 1024, "atoms smem (3 CTAs/SM)");
    static_assert(smemZ < 76 * 1024, "zmix smem (3 CTAs/SM)");

    cudaFuncSetAttribute((const void *)paths_kernel,
                         cudaFuncAttributeMaxDynamicSharedMemorySize, smemP);
    cudaFuncSetAttribute((const void *)atoms_kernel,
                         cudaFuncAttributeMaxDynamicSharedMemorySize, smemA);
    cudaFuncSetAttribute((const void *)zmix_kernel,
                         cudaFuncAttributeMaxDynamicSharedMemorySize, smemZ);

    zmix_kernel<<<456, 256, smemZ>>>(x, Wa5, ba5, Wa6, ba6);

    paths_kernel<<<2 * PBLK, 512, smemP>>>(xp5, xp6, row5, row6,
                                           Wc5, bc5, Wc6, bc6,
                                           xp5_out, xp6_out);

    atoms_kernel<<<456, 256, smemA>>>(x, Wp5, bp5, Wp6, bp6, x_out);
}